// round 3
// baseline (speedup 1.0000x reference)
#include <cuda_runtime.h>
#include <cuda_bf16.h>
#include <mma.h>
#include <cstdint>

using namespace nvcuda;

// ---------------- problem constants ----------------
constexpr int Bv   = 64;
constexpr int Hv   = 56;
constexpr int Wv   = 56;
constexpr int Cv   = 192;
constexpr int HEADS= 6;
constexpr int WS   = 7;
constexpr int SS   = 3;
constexpr int MLPD = 768;
constexpr int NT   = 49;              // tokens per window
constexpr int NWIN = 64;              // windows per image
constexpr int HD   = 32;              // head dim
constexpr int Lv   = Hv * Wv;         // 3136
constexpr int MT   = Bv * Lv;         // 200704 rows
constexpr float SCALE = 0.17677669529663687f; // 32^-0.5

// ---------------- device scratch (allocation-free rule: __device__ globals) ----
__device__ __nv_bfloat16 g_hwin[(size_t)MT * Cv];     // LN1 output, window-gathered
__device__ __nv_bfloat16 g_Q[(size_t)MT * Cv];
__device__ __nv_bfloat16 g_K[(size_t)MT * Cv];
__device__ __nv_bfloat16 g_V[(size_t)MT * Cv];
__device__ __nv_bfloat16 g_attn[(size_t)MT * Cv];     // attention out (window order)
__device__ float         g_x1[(size_t)MT * Cv];       // x + attn branch
__device__ __nv_bfloat16 g_h2n[(size_t)MT * Cv];      // LN2 output
__device__ __nv_bfloat16 g_mid[(size_t)MT * MLPD];    // gelu(mlp1)
__device__ __nv_bfloat16 g_wqkv[Cv * 3 * Cv];
__device__ __nv_bfloat16 g_wproj[Cv * Cv];
__device__ __nv_bfloat16 g_w1[Cv * MLPD];
__device__ __nv_bfloat16 g_w2[MLPD * Cv];

// ---------------- weight conversion fp32 -> bf16 ----------------
__global__ void cvt_weights(const float* __restrict__ qkvw,
                            const float* __restrict__ projw,
                            const float* __restrict__ w1,
                            const float* __restrict__ w2) {
    constexpr int n0 = Cv * 3 * Cv;      // 110592
    constexpr int n1 = Cv * Cv;          // 36864
    constexpr int n2 = Cv * MLPD;        // 147456
    constexpr int n3 = MLPD * Cv;        // 147456
    constexpr int tot = n0 + n1 + n2 + n3;
    for (int i = blockIdx.x * blockDim.x + threadIdx.x; i < tot;
         i += gridDim.x * blockDim.x) {
        if (i < n0)                  g_wqkv[i]            = __float2bfloat16(qkvw[i]);
        else if (i < n0 + n1)        g_wproj[i - n0]      = __float2bfloat16(projw[i - n0]);
        else if (i < n0 + n1 + n2)   g_w1[i - n0 - n1]    = __float2bfloat16(w1[i - n0 - n1]);
        else                         g_w2[i - n0 - n1 - n2]= __float2bfloat16(w2[i - n0 - n1 - n2]);
    }
}

// ---------------- LayerNorm kernels (one warp per row) ----------------
__global__ void ln1_kernel(const float* __restrict__ x,
                           const float* __restrict__ g,
                           const float* __restrict__ b) {
    int warp = threadIdx.x >> 5, lane = threadIdx.x & 31;
    int m = blockIdx.x * 8 + warp;                 // 0..MT-1
    // decode window-major index -> source image position (cyclic shift -SS gather)
    int win = m / NT, tok = m - win * NT;
    int bi  = win >> 6, wi = win & 63;
    int wh  = wi >> 3, ww = wi & 7;
    int ih  = tok / WS, iw = tok - ih * WS;
    int r   = (wh * WS + ih + SS) % Hv;
    int c   = (ww * WS + iw + SS) % Wv;
    const float* row = x + ((size_t)bi * Lv + r * Wv + c) * Cv;

    float v[6];
#pragma unroll
    for (int k = 0; k < 6; k++) v[k] = row[lane + 32 * k];
    float s = 0.f;
#pragma unroll
    for (int k = 0; k < 6; k++) s += v[k];
#pragma unroll
    for (int o = 16; o; o >>= 1) s += __shfl_xor_sync(0xffffffffu, s, o);
    float mean = s * (1.f / 192.f);
    float q = 0.f;
#pragma unroll
    for (int k = 0; k < 6; k++) { float d = v[k] - mean; q += d * d; }
#pragma unroll
    for (int o = 16; o; o >>= 1) q += __shfl_xor_sync(0xffffffffu, q, o);
    float rstd = rsqrtf(q * (1.f / 192.f) + 1e-5f);
#pragma unroll
    for (int k = 0; k < 6; k++) {
        int cc = lane + 32 * k;
        float y = (v[k] - mean) * rstd * g[cc] + b[cc];
        g_hwin[(size_t)m * Cv + cc] = __float2bfloat16(y);
    }
}

__global__ void ln2_kernel(const float* __restrict__ g,
                           const float* __restrict__ b) {
    int warp = threadIdx.x >> 5, lane = threadIdx.x & 31;
    int m = blockIdx.x * 8 + warp;
    const float* row = g_x1 + (size_t)m * Cv;
    float v[6];
#pragma unroll
    for (int k = 0; k < 6; k++) v[k] = row[lane + 32 * k];
    float s = 0.f;
#pragma unroll
    for (int k = 0; k < 6; k++) s += v[k];
#pragma unroll
    for (int o = 16; o; o >>= 1) s += __shfl_xor_sync(0xffffffffu, s, o);
    float mean = s * (1.f / 192.f);
    float q = 0.f;
#pragma unroll
    for (int k = 0; k < 6; k++) { float d = v[k] - mean; q += d * d; }
#pragma unroll
    for (int o = 16; o; o >>= 1) q += __shfl_xor_sync(0xffffffffu, q, o);
    float rstd = rsqrtf(q * (1.f / 192.f) + 1e-5f);
#pragma unroll
    for (int k = 0; k < 6; k++) {
        int cc = lane + 32 * k;
        float y = (v[k] - mean) * rstd * g[cc] + b[cc];
        g_h2n[(size_t)m * Cv + cc] = __float2bfloat16(y);
    }
}

// ---------------- shift-mask region helper ----------------
__device__ __forceinline__ int reg3(int r) { return r < 49 ? 0 : (r < 53 ? 1 : 2); }

// ---------------- attention kernel: one block per (window, head) ----------------
__global__ __launch_bounds__(256) void attn_kernel(const float* __restrict__ rpb) {
    int bid  = blockIdx.x;
    int win  = bid / HEADS, head = bid - win * HEADS;
    int wi   = win & 63;
    int wh   = wi >> 3, ww = wi & 7;

    __shared__ float qs[NT * HD];
    __shared__ float ks[NT * HD];
    __shared__ float vs[NT * HD];
    __shared__ float ps[NT * 50];

    size_t base = (size_t)bid * (NT * HD);
    for (int e = threadIdx.x; e < NT * HD; e += 256) {
        qs[e] = __bfloat162float(g_Q[base + e]);
        ks[e] = __bfloat162float(g_K[base + e]);
        vs[e] = __bfloat162float(g_V[base + e]);
    }
    __syncthreads();

    for (int e = threadIdx.x; e < NT * NT; e += 256) {
        int i = e / NT, j = e - i * NT;
        const float* qp = &qs[i * HD];
        const float* kp = &ks[j * HD];
        float s = 0.f;
#pragma unroll
        for (int d = 0; d < HD; d++) s += qp[d] * kp[d];
        int ih = i / WS, iw = i - ih * WS;
        int jh = j / WS, jw = j - jh * WS;
        int idx = (ih - jh + WS - 1) * (2 * WS - 1) + (iw - jw + WS - 1);
        s += rpb[idx * HEADS + head];
        int li = reg3(wh * WS + ih) * 3 + reg3(ww * WS + iw);
        int lj = reg3(wh * WS + jh) * 3 + reg3(ww * WS + jw);
        if (li != lj) s -= 100.f;
        ps[i * 50 + j] = s;
    }
    __syncthreads();

    int warp = threadIdx.x >> 5, lane = threadIdx.x & 31;
    for (int row = warp; row < NT; row += 8) {
        float v0 = ps[row * 50 + lane];
        bool  h2 = (lane + 32) < NT;
        float v1 = h2 ? ps[row * 50 + lane + 32] : -1e30f;
        float mx = fmaxf(v0, v1);
#pragma unroll
        for (int o = 16; o; o >>= 1) mx = fmaxf(mx, __shfl_xor_sync(0xffffffffu, mx, o));
        float e0 = __expf(v0 - mx);
        float e1 = h2 ? __expf(v1 - mx) : 0.f;
        float sm = e0 + e1;
#pragma unroll
        for (int o = 16; o; o >>= 1) sm += __shfl_xor_sync(0xffffffffu, sm, o);
        float inv = 1.f / sm;
        ps[row * 50 + lane] = e0 * inv;
        if (h2) ps[row * 50 + lane + 32] = e1 * inv;
    }
    __syncthreads();

    for (int e = threadIdx.x; e < NT * HD; e += 256) {
        int i = e >> 5, d = e & 31;
        float s = 0.f;
#pragma unroll
        for (int j = 0; j < NT; j++) s += ps[i * 50 + j] * vs[j * HD + d];
        g_attn[((size_t)win * NT + i) * Cv + head * HD + d] = __float2bfloat16(s);
    }
}

// ---------------- fused bf16 wmma GEMM with templated epilogue ----------------
// EPI 0: hwin @ wqkv (K=192,N=576) -> +bias, q*=SCALE, split Q/K/V bf16
// EPI 1: attn @ wproj (K=192,N=192) -> +bias, window-reverse + roll, x1 = x + out
// EPI 2: h2n @ w1    (K=192,N=768) -> +bias, exact gelu, bf16 -> g_mid
// EPI 3: mid @ w2    (K=768,N=192) -> +bias, out = x1 + val (fp32 d_out)
template <int EPI>
__global__ __launch_bounds__(256) void gemm_k(const float* __restrict__ bias,
                                              const float* __restrict__ xin,
                                              float* __restrict__ outf) {
    constexpr int K = (EPI == 3) ? MLPD : Cv;
    constexpr int N = (EPI == 0) ? 3 * Cv : (EPI == 2) ? MLPD : Cv;

    const __nv_bfloat16* __restrict__ A =
        (EPI == 0) ? g_hwin : (EPI == 1) ? g_attn : (EPI == 2) ? g_h2n : g_mid;
    const __nv_bfloat16* __restrict__ Bm =
        (EPI == 0) ? g_wqkv : (EPI == 1) ? g_wproj : (EPI == 2) ? g_w1 : g_w2;

    __shared__ __align__(16) unsigned char smbuf[128 * 68 * 4];
    __nv_bfloat16* As = (__nv_bfloat16*)smbuf;                  // [128][40]
    __nv_bfloat16* Bs = (__nv_bfloat16*)(smbuf + 128 * 40 * 2); // [32][72]
    float*         Cs = (float*)smbuf;                          // [128][68]

    const int tid = threadIdx.x;
    const int m0 = blockIdx.y * 128;
    const int n0 = blockIdx.x * 64;
    const int warp = tid >> 5, wm = warp >> 1, wn = warp & 1;

    wmma::fragment<wmma::accumulator, 16, 16, 16, float> acc[2][2];
#pragma unroll
    for (int i = 0; i < 2; i++)
#pragma unroll
        for (int j = 0; j < 2; j++) wmma::fill_fragment(acc[i][j], 0.f);

    for (int k0 = 0; k0 < K; k0 += 32) {
#pragma unroll
        for (int it = 0; it < 2; it++) {
            int v = tid + it * 256;
            int r = v >> 2, c8 = (v & 3) * 8;
            *(uint4*)&As[r * 40 + c8] =
                *(const uint4*)&A[(size_t)(m0 + r) * K + k0 + c8];
        }
        {
            int r = tid >> 3, c8 = (tid & 7) * 8;
            *(uint4*)&Bs[r * 72 + c8] =
                *(const uint4*)&Bm[(size_t)(k0 + r) * N + n0 + c8];
        }
        __syncthreads();
#pragma unroll
        for (int kk = 0; kk < 32; kk += 16) {
            wmma::fragment<wmma::matrix_a, 16, 16, 16, __nv_bfloat16, wmma::row_major> af[2];
            wmma::fragment<wmma::matrix_b, 16, 16, 16, __nv_bfloat16, wmma::row_major> bfr[2];
            wmma::load_matrix_sync(af[0], &As[(wm * 32 + 0)  * 40 + kk], 40);
            wmma::load_matrix_sync(af[1], &As[(wm * 32 + 16) * 40 + kk], 40);
            wmma::load_matrix_sync(bfr[0], &Bs[kk * 72 + wn * 32 + 0],  72);
            wmma::load_matrix_sync(bfr[1], &Bs[kk * 72 + wn * 32 + 16], 72);
#pragma unroll
            for (int i = 0; i < 2; i++)
#pragma unroll
                for (int j = 0; j < 2; j++)
                    wmma::mma_sync(acc[i][j], af[i], bfr[j], acc[i][j]);
        }
        __syncthreads();
    }

#pragma unroll
    for (int i = 0; i < 2; i++)
#pragma unroll
        for (int j = 0; j < 2; j++)
            wmma::store_matrix_sync(&Cs[(wm * 32 + i * 16) * 68 + wn * 32 + j * 16],
                                    acc[i][j], 68, wmma::mem_row_major);
    __syncthreads();

    for (int e = tid; e < 128 * 64; e += 256) {
        int r = e >> 6, c = e & 63;
        int m = m0 + r, n = n0 + c;
        float v = Cs[r * 68 + c] + bias[n];
        if constexpr (EPI == 0) {
            int sel = n / Cv, w2 = n - sel * Cv;
            int head = w2 >> 5, d = w2 & 31;
            int win = m / NT, tok = m - win * NT;
            size_t dst = ((size_t)(win * HEADS + head) * NT + tok) * HD + d;
            if (sel == 0)      g_Q[dst] = __float2bfloat16(v * SCALE);
            else if (sel == 1) g_K[dst] = __float2bfloat16(v);
            else               g_V[dst] = __float2bfloat16(v);
        } else if constexpr (EPI == 1) {
            int win = m / NT, tok = m - win * NT;
            int bi = win >> 6, wi = win & 63;
            int wh = wi >> 3, ww = wi & 7;
            int ih = tok / WS, iw = tok - ih * WS;
            int r2 = (wh * WS + ih + SS) % Hv;
            int c2 = (ww * WS + iw + SS) % Wv;
            size_t pos = ((size_t)bi * Lv + r2 * Wv + c2) * Cv + n;
            g_x1[pos] = xin[pos] + v;
        } else if constexpr (EPI == 2) {
            float ge = 0.5f * v * (1.f + erff(v * 0.70710678118654752f));
            g_mid[(size_t)m * MLPD + n] = __float2bfloat16(ge);
        } else {
            size_t pos = (size_t)m * Cv + n;
            outf[pos] = g_x1[pos] + v;
        }
    }
}

// ---------------- launch ----------------
extern "C" void kernel_launch(void* const* d_in, const int* in_sizes, int n_in,
                              void* d_out, int out_size) {
    const float* x      = (const float*)d_in[0];
    const float* ln1_g  = (const float*)d_in[1];
    const float* ln1_b  = (const float*)d_in[2];
    const float* qkv_w  = (const float*)d_in[3];
    const float* qkv_b  = (const float*)d_in[4];
    const float* proj_w = (const float*)d_in[5];
    const float* proj_b = (const float*)d_in[6];
    const float* rpb    = (const float*)d_in[7];
    const float* ln2_g  = (const float*)d_in[8];
    const float* ln2_b  = (const float*)d_in[9];
    const float* mlp_w1 = (const float*)d_in[10];
    const float* mlp_b1 = (const float*)d_in[11];
    const float* mlp_w2 = (const float*)d_in[12];
    const float* mlp_b2 = (const float*)d_in[13];
    float* out = (float*)d_out;

    cvt_weights<<<432, 1024>>>(qkv_w, proj_w, mlp_w1, mlp_w2);
    ln1_kernel<<<MT / 8, 256>>>(x, ln1_g, ln1_b);
    gemm_k<0><<<dim3(3 * Cv / 64, MT / 128), 256>>>(qkv_b, nullptr, nullptr);
    attn_kernel<<<Bv * NWIN * HEADS, 256>>>(rpb);
    gemm_k<1><<<dim3(Cv / 64, MT / 128), 256>>>(proj_b, x, nullptr);
    ln2_kernel<<<MT / 8, 256>>>(ln2_g, ln2_b);
    gemm_k<2><<<dim3(MLPD / 64, MT / 128), 256>>>(mlp_b1, nullptr, nullptr);
    gemm_k<3><<<dim3(Cv / 64, MT / 128), 256>>>(mlp_b2, nullptr, out);
}

// round 4
// speedup vs baseline: 2.0255x; 2.0255x over previous
#include <cuda_runtime.h>
#include <cuda_bf16.h>
#include <mma.h>
#include <cstdint>

using namespace nvcuda;

// ---------------- problem constants ----------------
constexpr int Bv   = 64;
constexpr int Hv   = 56;
constexpr int Wv   = 56;
constexpr int Cv   = 192;
constexpr int HEADS= 6;
constexpr int WS   = 7;
constexpr int SS   = 3;
constexpr int MLPD = 768;
constexpr int NT   = 49;              // tokens per window
constexpr int HD   = 32;              // head dim
constexpr int Lv   = Hv * Wv;         // 3136
constexpr int MT   = Bv * Lv;         // 200704 rows
constexpr float SCALE = 0.17677669529663687f; // 32^-0.5

// ---------------- device scratch ----------------
__device__ __nv_bfloat16 g_hwin[(size_t)MT * Cv];
__device__ __nv_bfloat16 g_Q[(size_t)MT * Cv];
__device__ __nv_bfloat16 g_K[(size_t)MT * Cv];
__device__ __nv_bfloat16 g_V[(size_t)MT * Cv];
__device__ __nv_bfloat16 g_attn[(size_t)MT * Cv];
__device__ float         g_x1[(size_t)MT * Cv];
__device__ __nv_bfloat16 g_h2n[(size_t)MT * Cv];
__device__ __nv_bfloat16 g_mid[(size_t)MT * MLPD];
__device__ __nv_bfloat16 g_wqkv[Cv * 3 * Cv];
__device__ __nv_bfloat16 g_wproj[Cv * Cv];
__device__ __nv_bfloat16 g_w1[Cv * MLPD];
__device__ __nv_bfloat16 g_w2[MLPD * Cv];
__device__ float         g_bm[64 * HEADS * NT * NT];   // bias+mask table (batch-invariant)

// ---------------- cp.async helpers ----------------
__device__ __forceinline__ void cp16(void* d, const void* s) {
    unsigned sa = (unsigned)__cvta_generic_to_shared(d);
    asm volatile("cp.async.cg.shared.global [%0], [%1], 16;" :: "r"(sa), "l"(s));
}
#define CP_COMMIT() asm volatile("cp.async.commit_group;")
#define CP_WAIT2()  asm volatile("cp.async.wait_group 2;")

// ---------------- weight conversion fp32 -> bf16 ----------------
__global__ void cvt_weights(const float* __restrict__ qkvw,
                            const float* __restrict__ projw,
                            const float* __restrict__ w1,
                            const float* __restrict__ w2) {
    constexpr int n0 = Cv * 3 * Cv;
    constexpr int n1 = Cv * Cv;
    constexpr int n2 = Cv * MLPD;
    constexpr int n3 = MLPD * Cv;
    constexpr int tot = n0 + n1 + n2 + n3;
    for (int i = blockIdx.x * blockDim.x + threadIdx.x; i < tot;
         i += gridDim.x * blockDim.x) {
        if (i < n0)                  g_wqkv[i]             = __float2bfloat16(qkvw[i]);
        else if (i < n0 + n1)        g_wproj[i - n0]       = __float2bfloat16(projw[i - n0]);
        else if (i < n0 + n1 + n2)   g_w1[i - n0 - n1]     = __float2bfloat16(w1[i - n0 - n1]);
        else                         g_w2[i - n0 - n1 - n2]= __float2bfloat16(w2[i - n0 - n1 - n2]);
    }
}

// ---------------- shift-mask region helper + bias table ----------------
__device__ __forceinline__ int reg3(int r) { return r < 49 ? 0 : (r < 53 ? 1 : 2); }

__global__ void bm_kernel(const float* __restrict__ rpb) {
    int e = blockIdx.x * blockDim.x + threadIdx.x;
    constexpr int TOT = 64 * HEADS * NT * NT;
    if (e >= TOT) return;
    int j   = e % NT;
    int i   = (e / NT) % NT;
    int h   = (e / (NT * NT)) % HEADS;
    int wi  = e / (NT * NT * HEADS);
    int wh = wi >> 3, ww = wi & 7;
    int ih = i / WS, iw = i - ih * WS;
    int jh = j / WS, jw = j - jh * WS;
    int idx = (ih - jh + WS - 1) * (2 * WS - 1) + (iw - jw + WS - 1);
    float v = rpb[idx * HEADS + h];
    int li = reg3(wh * WS + ih) * 3 + reg3(ww * WS + iw);
    int lj = reg3(wh * WS + jh) * 3 + reg3(ww * WS + jw);
    if (li != lj) v -= 100.f;
    g_bm[e] = v;
}

// ---------------- LayerNorm kernels (one warp per row) ----------------
__global__ void ln1_kernel(const float* __restrict__ x,
                           const float* __restrict__ g,
                           const float* __restrict__ b) {
    int warp = threadIdx.x >> 5, lane = threadIdx.x & 31;
    int m = blockIdx.x * 8 + warp;
    int win = m / NT, tok = m - win * NT;
    int bi  = win >> 6, wi = win & 63;
    int wh  = wi >> 3, ww = wi & 7;
    int ih  = tok / WS, iw = tok - ih * WS;
    int r   = (wh * WS + ih + SS) % Hv;
    int c   = (ww * WS + iw + SS) % Wv;
    const float* row = x + ((size_t)bi * Lv + r * Wv + c) * Cv;
    float v[6];
#pragma unroll
    for (int k = 0; k < 6; k++) v[k] = row[lane + 32 * k];
    float s = 0.f;
#pragma unroll
    for (int k = 0; k < 6; k++) s += v[k];
#pragma unroll
    for (int o = 16; o; o >>= 1) s += __shfl_xor_sync(0xffffffffu, s, o);
    float mean = s * (1.f / 192.f);
    float q = 0.f;
#pragma unroll
    for (int k = 0; k < 6; k++) { float d = v[k] - mean; q += d * d; }
#pragma unroll
    for (int o = 16; o; o >>= 1) q += __shfl_xor_sync(0xffffffffu, q, o);
    float rstd = rsqrtf(q * (1.f / 192.f) + 1e-5f);
#pragma unroll
    for (int k = 0; k < 6; k++) {
        int cc = lane + 32 * k;
        g_hwin[(size_t)m * Cv + cc] = __float2bfloat16((v[k] - mean) * rstd * g[cc] + b[cc]);
    }
}

__global__ void ln2_kernel(const float* __restrict__ g,
                           const float* __restrict__ b) {
    int warp = threadIdx.x >> 5, lane = threadIdx.x & 31;
    int m = blockIdx.x * 8 + warp;
    const float* row = g_x1 + (size_t)m * Cv;
    float v[6];
#pragma unroll
    for (int k = 0; k < 6; k++) v[k] = row[lane + 32 * k];
    float s = 0.f;
#pragma unroll
    for (int k = 0; k < 6; k++) s += v[k];
#pragma unroll
    for (int o = 16; o; o >>= 1) s += __shfl_xor_sync(0xffffffffu, s, o);
    float mean = s * (1.f / 192.f);
    float q = 0.f;
#pragma unroll
    for (int k = 0; k < 6; k++) { float d = v[k] - mean; q += d * d; }
#pragma unroll
    for (int o = 16; o; o >>= 1) q += __shfl_xor_sync(0xffffffffu, q, o);
    float rstd = rsqrtf(q * (1.f / 192.f) + 1e-5f);
#pragma unroll
    for (int k = 0; k < 6; k++) {
        int cc = lane + 32 * k;
        g_h2n[(size_t)m * Cv + cc] = __float2bfloat16((v[k] - mean) * rstd * g[cc] + b[cc]);
    }
}

// ---------------- tensor-core attention: one block per window ----------------
__global__ __launch_bounds__(256) void attn_wmma() {
    int win = blockIdx.x;              // 0..4095
    int wi  = win & 63;
    int tid = threadIdx.x, warp = tid >> 5, lane = tid & 31;

    __shared__ __align__(16) __nv_bfloat16 Qs[64 * 40];
    __shared__ __align__(16) __nv_bfloat16 Ks[64 * 40];
    __shared__ __align__(16) __nv_bfloat16 Vs[64 * 40];
    __shared__ __align__(16) float         Ss[64 * 68];   // aliased as Os [64*36]
    __shared__ __align__(16) __nv_bfloat16 Ps[64 * 72];
    float* Os = Ss;

    for (int head = 0; head < HEADS; head++) {
        size_t base = (size_t)(win * HEADS + head) * NT * HD;
        // load 49x32 Q/K/V tiles (196 uint4 each), zero V pad rows
        for (int id = tid; id < 196; id += 256) {
            int r = id >> 2, c8 = (id & 3) * 8;
            *(uint4*)&Qs[r * 40 + c8] = *(const uint4*)&g_Q[base + id * 8];
            *(uint4*)&Ks[r * 40 + c8] = *(const uint4*)&g_K[base + id * 8];
            *(uint4*)&Vs[r * 40 + c8] = *(const uint4*)&g_V[base + id * 8];
        }
        for (int id = tid; id < 60; id += 256) {       // rows 49..63 of V = 0
            int r = 49 + (id >> 2), c8 = (id & 3) * 8;
            *(uint4*)&Vs[r * 40 + c8] = make_uint4(0, 0, 0, 0);
        }
        __syncthreads();

        // S = Q @ K^T (64x64x32). warp -> (16-row strip, 32-col half)
        {
            int mrow = (warp >> 1) * 16, ncol = (warp & 1) * 32;
            wmma::fragment<wmma::accumulator, 16, 16, 16, float> acc[2];
            wmma::fill_fragment(acc[0], 0.f);
            wmma::fill_fragment(acc[1], 0.f);
#pragma unroll
            for (int kk = 0; kk < 32; kk += 16) {
                wmma::fragment<wmma::matrix_a, 16, 16, 16, __nv_bfloat16, wmma::row_major> af;
                wmma::load_matrix_sync(af, &Qs[mrow * 40 + kk], 40);
#pragma unroll
                for (int j = 0; j < 2; j++) {
                    wmma::fragment<wmma::matrix_b, 16, 16, 16, __nv_bfloat16, wmma::col_major> bf;
                    wmma::load_matrix_sync(bf, &Ks[(ncol + j * 16) * 40 + kk], 40);
                    wmma::mma_sync(acc[j], af, bf, acc[j]);
                }
            }
#pragma unroll
            for (int j = 0; j < 2; j++)
                wmma::store_matrix_sync(&Ss[mrow * 68 + ncol + j * 16], acc[j], 68,
                                        wmma::mem_row_major);
        }
        __syncthreads();

        // softmax rows 0..48 with precomputed bias+mask
        {
            const float* bmp = g_bm + (size_t)(wi * HEADS + head) * (NT * NT);
            for (int row = warp; row < NT; row += 8) {
                int j1 = lane + 32;
                float s0 = Ss[row * 68 + lane] + bmp[row * NT + lane];
                float s1 = (j1 < NT) ? Ss[row * 68 + j1] + bmp[row * NT + j1] : -1e30f;
                float mx = fmaxf(s0, s1);
#pragma unroll
                for (int o = 16; o; o >>= 1) mx = fmaxf(mx, __shfl_xor_sync(0xffffffffu, mx, o));
                float e0 = __expf(s0 - mx);
                float e1 = (j1 < NT) ? __expf(s1 - mx) : 0.f;
                float sm = e0 + e1;
#pragma unroll
                for (int o = 16; o; o >>= 1) sm += __shfl_xor_sync(0xffffffffu, sm, o);
                float inv = 1.f / sm;
                Ps[row * 72 + lane] = __float2bfloat16(e0 * inv);
                Ps[row * 72 + j1]   = __float2bfloat16(e1 * inv);  // 0 for pad cols
            }
        }
        __syncthreads();

        // O = P @ V (64x32x64). warp -> (16-row strip, 16-col half)
        {
            int mrow = (warp >> 1) * 16, ncol = (warp & 1) * 16;
            wmma::fragment<wmma::accumulator, 16, 16, 16, float> acc;
            wmma::fill_fragment(acc, 0.f);
#pragma unroll
            for (int kk = 0; kk < 64; kk += 16) {
                wmma::fragment<wmma::matrix_a, 16, 16, 16, __nv_bfloat16, wmma::row_major> af;
                wmma::fragment<wmma::matrix_b, 16, 16, 16, __nv_bfloat16, wmma::row_major> bf;
                wmma::load_matrix_sync(af, &Ps[mrow * 72 + kk], 72);
                wmma::load_matrix_sync(bf, &Vs[kk * 40 + ncol], 40);
                wmma::mma_sync(acc, af, bf, acc);
            }
            wmma::store_matrix_sync(&Os[mrow * 36 + ncol], acc, 36, wmma::mem_row_major);
        }
        __syncthreads();

        // write O rows < 49 to g_attn (window order, per-head columns)
        for (int e = tid; e < NT * HD; e += 256) {
            int r = e >> 5, d = e & 31;
            g_attn[((size_t)win * NT + r) * Cv + head * HD + d] =
                __float2bfloat16(Os[r * 36 + d]);
        }
        __syncthreads();
    }
}

// ---------------- pipelined bf16 wmma GEMM (cp.async, 3 stages, BK=32) --------
// EPI 0: hwin @ wqkv -> +bias, q*=SCALE, split Q/K/V
// EPI 1: attn @ wproj -> +bias, window-reverse + roll, x1 = x + out
// EPI 2: h2n @ w1    -> +bias, exact gelu -> g_mid
// EPI 3: mid @ w2    -> +bias, out = x1 + val
template <int EPI>
__global__ __launch_bounds__(256) void gemm_k(const float* __restrict__ bias,
                                              const float* __restrict__ xin,
                                              float* __restrict__ outf) {
    constexpr int K = (EPI == 3) ? MLPD : Cv;
    constexpr int N = (EPI == 0) ? 3 * Cv : (EPI == 2) ? MLPD : Cv;
    constexpr int BK = 32;
    constexpr int NK = K / BK;

    const __nv_bfloat16* __restrict__ A =
        (EPI == 0) ? g_hwin : (EPI == 1) ? g_attn : (EPI == 2) ? g_h2n : g_mid;
    const __nv_bfloat16* __restrict__ Bm =
        (EPI == 0) ? g_wqkv : (EPI == 1) ? g_wproj : (EPI == 2) ? g_w1 : g_w2;

    // smem: 3-stage A[128][40] + B[32][72], epilogue reuses as Cs[128][68] fp32
    __shared__ __align__(16) unsigned char smbuf[3 * 128 * 40 * 2 + 3 * 32 * 72 * 2];
    __nv_bfloat16* As = (__nv_bfloat16*)smbuf;
    __nv_bfloat16* Bs = (__nv_bfloat16*)(smbuf + 3 * 128 * 40 * 2);
    float*         Cs = (float*)smbuf;

    const int tid = threadIdx.x;
    const int m0 = blockIdx.y * 128;
    const int n0 = blockIdx.x * 64;
    const int warp = tid >> 5, wm = warp >> 1, wn = warp & 1;

    auto load_stage = [&](int kt, int stg) {
        int k0 = kt * BK;
        __nv_bfloat16* as = As + stg * (128 * 40);
        __nv_bfloat16* bs = Bs + stg * (32 * 72);
#pragma unroll
        for (int i = 0; i < 2; i++) {
            int id = tid + i * 256;
            int r = id >> 2, c8 = (id & 3) * 8;
            cp16(&as[r * 40 + c8], &A[(size_t)(m0 + r) * K + k0 + c8]);
        }
        {
            int r = tid >> 3, c8 = (tid & 7) * 8;
            cp16(&bs[r * 72 + c8], &Bm[(size_t)(k0 + r) * N + n0 + c8]);
        }
    };

    wmma::fragment<wmma::accumulator, 16, 16, 16, float> acc[2][2];
#pragma unroll
    for (int i = 0; i < 2; i++)
#pragma unroll
        for (int j = 0; j < 2; j++) wmma::fill_fragment(acc[i][j], 0.f);

    load_stage(0, 0); CP_COMMIT();
    load_stage(1, 1); CP_COMMIT();

    for (int kt = 0; kt < NK; kt++) {
        if (kt + 2 < NK) load_stage(kt + 2, (kt + 2) % 3);
        CP_COMMIT();
        CP_WAIT2();
        __syncthreads();
        const __nv_bfloat16* as = As + (kt % 3) * (128 * 40);
        const __nv_bfloat16* bs = Bs + (kt % 3) * (32 * 72);
#pragma unroll
        for (int kk = 0; kk < BK; kk += 16) {
            wmma::fragment<wmma::matrix_a, 16, 16, 16, __nv_bfloat16, wmma::row_major> af[2];
            wmma::fragment<wmma::matrix_b, 16, 16, 16, __nv_bfloat16, wmma::row_major> bfr[2];
            wmma::load_matrix_sync(af[0], &as[(wm * 32 + 0)  * 40 + kk], 40);
            wmma::load_matrix_sync(af[1], &as[(wm * 32 + 16) * 40 + kk], 40);
            wmma::load_matrix_sync(bfr[0], &bs[kk * 72 + wn * 32 + 0],  72);
            wmma::load_matrix_sync(bfr[1], &bs[kk * 72 + wn * 32 + 16], 72);
#pragma unroll
            for (int i = 0; i < 2; i++)
#pragma unroll
                for (int j = 0; j < 2; j++)
                    wmma::mma_sync(acc[i][j], af[i], bfr[j], acc[i][j]);
        }
        __syncthreads();
    }

#pragma unroll
    for (int i = 0; i < 2; i++)
#pragma unroll
        for (int j = 0; j < 2; j++)
            wmma::store_matrix_sync(&Cs[(wm * 32 + i * 16) * 68 + wn * 32 + j * 16],
                                    acc[i][j], 68, wmma::mem_row_major);
    __syncthreads();

    for (int e = tid; e < 128 * 64; e += 256) {
        int r = e >> 6, c = e & 63;
        int m = m0 + r, n = n0 + c;
        float v = Cs[r * 68 + c] + bias[n];
        if constexpr (EPI == 0) {
            int sel = n / Cv, w2 = n - sel * Cv;
            int head = w2 >> 5, d = w2 & 31;
            int win = m / NT, tok = m - win * NT;
            size_t dst = ((size_t)(win * HEADS + head) * NT + tok) * HD + d;
            if (sel == 0)      g_Q[dst] = __float2bfloat16(v * SCALE);
            else if (sel == 1) g_K[dst] = __float2bfloat16(v);
            else               g_V[dst] = __float2bfloat16(v);
        } else if constexpr (EPI == 1) {
            int win = m / NT, tok = m - win * NT;
            int bi = win >> 6, wi = win & 63;
            int wh = wi >> 3, ww = wi & 7;
            int ih = tok / WS, iw = tok - ih * WS;
            int r2 = (wh * WS + ih + SS) % Hv;
            int c2 = (ww * WS + iw + SS) % Wv;
            size_t pos = ((size_t)bi * Lv + r2 * Wv + c2) * Cv + n;
            g_x1[pos] = xin[pos] + v;
        } else if constexpr (EPI == 2) {
            float ge = 0.5f * v * (1.f + erff(v * 0.70710678118654752f));
            g_mid[(size_t)m * MLPD + n] = __float2bfloat16(ge);
        } else {
            size_t pos = (size_t)m * Cv + n;
            outf[pos] = g_x1[pos] + v;
        }
    }
}

// ---------------- launch ----------------
extern "C" void kernel_launch(void* const* d_in, const int* in_sizes, int n_in,
                              void* d_out, int out_size) {
    const float* x      = (const float*)d_in[0];
    const float* ln1_g  = (const float*)d_in[1];
    const float* ln1_b  = (const float*)d_in[2];
    const float* qkv_w  = (const float*)d_in[3];
    const float* qkv_b  = (const float*)d_in[4];
    const float* proj_w = (const float*)d_in[5];
    const float* proj_b = (const float*)d_in[6];
    const float* rpb    = (const float*)d_in[7];
    const float* ln2_g  = (const float*)d_in[8];
    const float* ln2_b  = (const float*)d_in[9];
    const float* mlp_w1 = (const float*)d_in[10];
    const float* mlp_b1 = (const float*)d_in[11];
    const float* mlp_w2 = (const float*)d_in[12];
    const float* mlp_b2 = (const float*)d_in[13];
    float* out = (float*)d_out;

    cvt_weights<<<432, 1024>>>(qkv_w, proj_w, mlp_w1, mlp_w2);
    bm_kernel<<<(64 * HEADS * NT * NT + 255) / 256, 256>>>(rpb);
    ln1_kernel<<<MT / 8, 256>>>(x, ln1_g, ln1_b);
    gemm_k<0><<<dim3(3 * Cv / 64, MT / 128), 256>>>(qkv_b, nullptr, nullptr);
    attn_wmma<<<Bv * 64, 256>>>();
    gemm_k<1><<<dim3(Cv / 64, MT / 128), 256>>>(proj_b, x, nullptr);
    ln2_kernel<<<MT / 8, 256>>>(ln2_g, ln2_b);
    gemm_k<2><<<dim3(MLPD / 64, MT / 128), 256>>>(mlp_b1, nullptr, nullptr);
    gemm_k<3><<<dim3(Cv / 64, MT / 128), 256>>>(mlp_b2, nullptr, out);
}